// round 5
// baseline (speedup 1.0000x reference)
#include <cuda_runtime.h>
#include <math.h>

// Depthwise 5x5 Gaussian blur, separable, fully warp-autonomous.
// One warp = one 8-row x 64-col strip. It loads 12 rows (8 + 4 halo,
// warp-uniform zero-padding at image edges), does the horizontal pass in
// registers via full-warp shuffles, vertical pass on the middle 8 rows.
// No shared memory, no __syncthreads.
// x: [16, 256, 64, 64] f32, sigma: [1] f32.

#define HH 64
#define WW 64
#define TPB 256   // 8 warps = 8 strips = one full 64x64 plane per block

__global__ __launch_bounds__(TPB) void gauss5_kernel(const float* __restrict__ x,
                                                     const float* __restrict__ sigma_p,
                                                     float* __restrict__ out)
{
    const int tid  = threadIdx.x;
    const int rb   = tid >> 5;        // strip index within plane (0..7)
    const int lane = tid & 31;        // float2 column group (0..31)

    const int plane = blockIdx.x;
    const float2* gin  = reinterpret_cast<const float2*>(x)   + plane * 2048;
    float2*       gout = reinterpret_cast<float2*>(out)       + plane * 2048;

    // Gaussian taps (symmetric), center tap folded to 1; normalize at the end.
    const float sigma = sigma_p[0];
    const float inv2s2 = 1.0f / (2.0f * sigma * sigma);
    const float g0 = expf(-4.0f * inv2s2);   // |d| = 2
    const float g1 = expf(-1.0f * inv2s2);   // |d| = 1
    const float s1 = 2.0f * (g0 + g1) + 1.0f;
    const float invn = 1.0f / (s1 * s1);

    const int row0 = (rb << 3) - 2;   // first halo row of this strip

    // --- load 12 rows + horizontal pass, all in registers ---
    float2 t[12];
    #pragma unroll
    for (int j = 0; j < 12; j++) {
        int r = row0 + j;
        if (r < 0 || r >= HH) {               // warp-uniform predicate
            t[j] = make_float2(0.0f, 0.0f);
        } else {
            float2 b = gin[r * 32 + lane];
            float px = __shfl_up_sync(0xffffffffu, b.x, 1);    // col 2c-2
            float py = __shfl_up_sync(0xffffffffu, b.y, 1);    // col 2c-1
            float nx = __shfl_down_sync(0xffffffffu, b.x, 1);  // col 2c+2
            float ny = __shfl_down_sync(0xffffffffu, b.y, 1);  // col 2c+3
            if (lane == 0)  { px = 0.0f; py = 0.0f; }          // left zero-pad
            if (lane == 31) { nx = 0.0f; ny = 0.0f; }          // right zero-pad
            t[j].x = g0 * (px + nx) + g1 * (py + b.y) + b.x;
            t[j].y = g0 * (py + ny) + g1 * (b.x + nx) + b.y;
        }
    }

    // --- vertical pass on the middle 8 rows + store ---
    const int base = (rb << 3) * 32 + lane;
    #pragma unroll
    for (int j = 0; j < 8; j++) {
        float2 o;
        o.x = (g0 * (t[j].x + t[j+4].x) + g1 * (t[j+1].x + t[j+3].x) + t[j+2].x) * invn;
        o.y = (g0 * (t[j].y + t[j+4].y) + g1 * (t[j+1].y + t[j+3].y) + t[j+2].y) * invn;
        gout[base + j * 32] = o;
    }
}

extern "C" void kernel_launch(void* const* d_in, const int* in_sizes, int n_in,
                              void* d_out, int out_size) {
    const float* x = (const float*)d_in[0];
    const float* sigma = (const float*)d_in[1];
    float* out = (float*)d_out;
    int planes = in_sizes[0] / (HH * WW);   // 4096
    gauss5_kernel<<<planes, TPB>>>(x, sigma, out);
}

// round 6
// speedup vs baseline: 1.0948x; 1.0948x over previous
#include <cuda_runtime.h>
#include <math.h>

// Depthwise 5x5 Gaussian blur, separable. R4 structure (best so far):
// warp-row shuffles for horizontal, 8-row register tile + compact smem
// boundary exchange for vertical. NEW: packed f32x2 math (SASS FFMA2) for
// the filter arithmetic, 64-bit row carriers end-to-end, streaming stores.
// x: [16, 256, 64, 64] f32, sigma: [1] f32. One plane per 256-thread block.

#define HH 64
#define WW 64
#define TPB 256

typedef unsigned long long u64;

__device__ __forceinline__ u64 pack2(float lo, float hi) {
    u64 r; asm("mov.b64 %0, {%1, %2};" : "=l"(r) : "f"(lo), "f"(hi)); return r;
}
__device__ __forceinline__ u64 add2(u64 a, u64 b) {
    u64 r; asm("add.rn.f32x2 %0, %1, %2;" : "=l"(r) : "l"(a), "l"(b)); return r;
}
__device__ __forceinline__ u64 mul2(u64 a, u64 b) {
    u64 r; asm("mul.rn.f32x2 %0, %1, %2;" : "=l"(r) : "l"(a), "l"(b)); return r;
}
__device__ __forceinline__ u64 fma2(u64 a, u64 b, u64 c) {
    u64 r; asm("fma.rn.f32x2 %0, %1, %2, %3;" : "=l"(r) : "l"(a), "l"(b), "l"(c)); return r;
}

__global__ __launch_bounds__(TPB) void gauss5_kernel(const float* __restrict__ x,
                                                     const float* __restrict__ sigma_p,
                                                     float* __restrict__ out)
{
    // boundary buffer: 9 groups x 4 row-slots x 32 packed-row values.
    // group b holds horiz-result rows 8b-2, 8b-1, 8b, 8b+1 (slots 0..3)
    __shared__ u64 sbuf[9 * 4 * 32];   // 9 KB

    const int tid  = threadIdx.x;
    const int rb   = tid >> 5;         // 8-row strip index (0..7)
    const int lane = tid & 31;         // float2 column group (0..31)

    const int plane = blockIdx.x;
    const float2* gin  = reinterpret_cast<const float2*>(x) + plane * 2048;
    u64*          gout = reinterpret_cast<u64*>(out)        + plane * 2048;

    // Gaussian taps (symmetric), center tap folded to 1; normalize at the end.
    const float sigma = sigma_p[0];
    const float inv2s2 = 1.0f / (2.0f * sigma * sigma);
    const float g0 = expf(-4.0f * inv2s2);   // |d| = 2
    const float g1 = expf(-1.0f * inv2s2);   // |d| = 1
    const float s1 = 2.0f * (g0 + g1) + 1.0f;
    const float invn = 1.0f / (s1 * s1);

    const u64 G0   = pack2(g0, g0);
    const u64 G1   = pack2(g1, g1);
    const u64 INVN = pack2(invn, invn);

    // zero halo rows: plane rows (-2,-1) -> group 0 slots 0,1
    //                 plane rows (64,65) -> group 8 slots 2,3
    if (tid < 128) {
        int hr = tid >> 5;             // 0..3
        int c  = tid & 31;
        int g  = (hr < 2) ? 0 : 8;
        sbuf[(g * 4 + hr) * 32 + c] = 0ULL;
    }

    const int base = (rb << 3) * 32 + lane;   // float2 index of (row rb*8, col pair)

    // --- load 8 rows + horizontal pass; outputs stay packed ---
    u64 t[8];
    #pragma unroll
    for (int j = 0; j < 8; j++) {
        float2 b = gin[base + j * 32];
        float px = __shfl_up_sync(0xffffffffu, b.x, 1);    // col 2c-2
        float py = __shfl_up_sync(0xffffffffu, b.y, 1);    // col 2c-1
        float nx = __shfl_down_sync(0xffffffffu, b.x, 1);  // col 2c+2
        float ny = __shfl_down_sync(0xffffffffu, b.y, 1);  // col 2c+3
        if (lane == 0)  { px = 0.0f; py = 0.0f; }          // left zero-pad
        if (lane == 31) { nx = 0.0f; ny = 0.0f; }          // right zero-pad
        // t = g1*(py+b.y, b.x+nx) + g0*(px+nx, py+ny) + (b.x, b.y)
        u64 v = pack2(py + b.y, b.x + nx);
        u64 u = pack2(px + nx, py + ny);
        u64 r = fma2(G1, v, pack2(b.x, b.y));
        t[j] = fma2(G0, u, r);
    }

    // --- share boundary rows through smem ---
    sbuf[(rb * 4 + 2) * 32 + lane]       = t[0];   // row 8rb
    sbuf[(rb * 4 + 3) * 32 + lane]       = t[1];   // row 8rb+1
    sbuf[((rb + 1) * 4 + 0) * 32 + lane] = t[6];   // row 8rb+6
    sbuf[((rb + 1) * 4 + 1) * 32 + lane] = t[7];   // row 8rb+7
    __syncthreads();

    u64 w[12];
    w[0]  = sbuf[(rb * 4 + 0) * 32 + lane];        // row 8rb-2
    w[1]  = sbuf[(rb * 4 + 1) * 32 + lane];        // row 8rb-1
    #pragma unroll
    for (int j = 0; j < 8; j++) w[2 + j] = t[j];
    w[10] = sbuf[((rb + 1) * 4 + 2) * 32 + lane];  // row 8rb+8
    w[11] = sbuf[((rb + 1) * 4 + 3) * 32 + lane];  // row 8rb+9

    // --- vertical pass, packed; streaming 64-bit stores ---
    #pragma unroll
    for (int j = 0; j < 8; j++) {
        u64 s1v = add2(w[j],     w[j + 4]);
        u64 s2v = add2(w[j + 1], w[j + 3]);
        u64 o = fma2(G0, s1v, w[j + 2]);
        o = fma2(G1, s2v, o);
        o = mul2(o, INVN);
        __stcs(gout + base + j * 32, o);
    }
}

extern "C" void kernel_launch(void* const* d_in, const int* in_sizes, int n_in,
                              void* d_out, int out_size) {
    const float* x = (const float*)d_in[0];
    const float* sigma = (const float*)d_in[1];
    float* out = (float*)d_out;
    int planes = in_sizes[0] / (HH * WW);   // 4096
    gauss5_kernel<<<planes, TPB>>>(x, sigma, out);
}

// round 7
// speedup vs baseline: 1.3042x; 1.1913x over previous
#include <cuda_runtime.h>
#include <math.h>

// Depthwise 5x5 Gaussian blur, separable, software-pipelined over planes.
// Each 256-thread block processes PPB=4 consecutive 64x64 planes. At the top
// of each plane-iteration it issues the NEXT plane's loads, then computes the
// current plane (warp-shuffle horizontal, 8-row register tile vertical with
// compact smem boundary exchange, ping-pong buffers, 1 barrier per plane).
// x: [16, 256, 64, 64] f32, sigma: [1] f32.

#define HH 64
#define WW 64
#define TPB 256
#define PPB 4

__global__ __launch_bounds__(TPB) void gauss5_kernel(const float* __restrict__ x,
                                                     const float* __restrict__ sigma_p,
                                                     float* __restrict__ out)
{
    // ping-pong boundary buffers: 9 groups x 4 row-slots x 32 float2 each.
    // group b holds horiz-result rows 8b-2, 8b-1, 8b, 8b+1 (slots 0..3).
    __shared__ float2 sbuf[2][9 * 4 * 32];   // 18 KB

    const int tid  = threadIdx.x;
    const int rb   = tid >> 5;        // 8-row strip index (0..7)
    const int lane = tid & 31;        // float2 column group (0..31)

    const long plane0 = (long)blockIdx.x * PPB;
    const float2* gin  = reinterpret_cast<const float2*>(x)   + plane0 * 2048;
    float2*       gout = reinterpret_cast<float2*>(out)       + plane0 * 2048;

    // Gaussian taps (symmetric), center tap folded to 1; normalize at the end.
    const float sigma = sigma_p[0];
    const float inv2s2 = 1.0f / (2.0f * sigma * sigma);
    const float g0 = expf(-4.0f * inv2s2);   // |d| = 2
    const float g1 = expf(-1.0f * inv2s2);   // |d| = 1
    const float s1 = 2.0f * (g0 + g1) + 1.0f;
    const float invn = 1.0f / (s1 * s1);

    // zero halo rows in BOTH buffers (never overwritten by data):
    // plane rows (-2,-1) -> group 0 slots 0,1 ; rows (64,65) -> group 8 slots 2,3
    {
        int buf = tid >> 7;           // 0/1
        int idx = tid & 127;
        int hr  = idx >> 5;           // 0..3
        int c   = idx & 31;
        int g   = (hr < 2) ? 0 : 8;
        sbuf[buf][(g * 4 + hr) * 32 + c] = make_float2(0.f, 0.f);
    }

    const int base = (rb << 3) * 32 + lane;   // float2 index of (row rb*8, col pair)

    // preload plane 0
    float2 cur[8];
    #pragma unroll
    for (int j = 0; j < 8; j++) cur[j] = gin[base + j * 32];

    #pragma unroll
    for (int p = 0; p < PPB; p++) {
        // issue next plane's loads early (independent of current compute)
        float2 nxt[8];
        if (p + 1 < PPB) {
            #pragma unroll
            for (int j = 0; j < 8; j++) nxt[j] = gin[(p + 1) * 2048 + base + j * 32];
        }

        // --- horizontal pass on current plane (registers + warp shuffles) ---
        float2 t[8];
        #pragma unroll
        for (int j = 0; j < 8; j++) {
            float2 b = cur[j];
            float px = __shfl_up_sync(0xffffffffu, b.x, 1);    // col 2c-2
            float py = __shfl_up_sync(0xffffffffu, b.y, 1);    // col 2c-1
            float nx = __shfl_down_sync(0xffffffffu, b.x, 1);  // col 2c+2
            float ny = __shfl_down_sync(0xffffffffu, b.y, 1);  // col 2c+3
            if (lane == 0)  { px = 0.0f; py = 0.0f; }          // left zero-pad
            if (lane == 31) { nx = 0.0f; ny = 0.0f; }          // right zero-pad
            t[j].x = g0 * (px + nx) + g1 * (py + b.y) + b.x;
            t[j].y = g0 * (py + ny) + g1 * (b.x + nx) + b.y;
        }

        // --- boundary exchange through ping-pong smem ---
        float2* sp = sbuf[p & 1];
        sp[(rb * 4 + 2) * 32 + lane]       = t[0];   // row 8rb
        sp[(rb * 4 + 3) * 32 + lane]       = t[1];   // row 8rb+1
        sp[((rb + 1) * 4 + 0) * 32 + lane] = t[6];   // row 8rb+6
        sp[((rb + 1) * 4 + 1) * 32 + lane] = t[7];   // row 8rb+7
        __syncthreads();

        float2 w[12];
        w[0]  = sp[(rb * 4 + 0) * 32 + lane];        // row 8rb-2
        w[1]  = sp[(rb * 4 + 1) * 32 + lane];        // row 8rb-1
        #pragma unroll
        for (int j = 0; j < 8; j++) w[2 + j] = t[j];
        w[10] = sp[((rb + 1) * 4 + 2) * 32 + lane];  // row 8rb+8
        w[11] = sp[((rb + 1) * 4 + 3) * 32 + lane];  // row 8rb+9

        // --- vertical pass + streaming stores ---
        float2* go = gout + p * 2048 + base;
        #pragma unroll
        for (int j = 0; j < 8; j++) {
            float2 o;
            o.x = (g0 * (w[j].x + w[j+4].x) + g1 * (w[j+1].x + w[j+3].x) + w[j+2].x) * invn;
            o.y = (g0 * (w[j].y + w[j+4].y) + g1 * (w[j+1].y + w[j+3].y) + w[j+2].y) * invn;
            __stcs(go + j * 32, o);
        }

        // rotate pipeline
        if (p + 1 < PPB) {
            #pragma unroll
            for (int j = 0; j < 8; j++) cur[j] = nxt[j];
        }
    }
}

extern "C" void kernel_launch(void* const* d_in, const int* in_sizes, int n_in,
                              void* d_out, int out_size) {
    const float* x = (const float*)d_in[0];
    const float* sigma = (const float*)d_in[1];
    float* out = (float*)d_out;
    int planes = in_sizes[0] / (HH * WW);   // 4096
    gauss5_kernel<<<planes / PPB, TPB>>>(x, sigma, out);
}

// round 8
// speedup vs baseline: 1.3062x; 1.0015x over previous
#include <cuda_runtime.h>
#include <math.h>

// Depthwise 5x5 Gaussian blur, separable, software-pipelined over planes,
// with barrier-shadow scheduling: boundary rows are exchanged early and the
// 4 interior output rows are computed+stored BEFORE the barrier; only the 4
// edge rows wait on shared memory.
// x: [16, 256, 64, 64] f32, sigma: [1] f32. PPB=4 planes per 256-thread block.

#define HH 64
#define WW 64
#define TPB 256
#define PPB 4

__global__ __launch_bounds__(TPB) void gauss5_kernel(const float* __restrict__ x,
                                                     const float* __restrict__ sigma_p,
                                                     float* __restrict__ out)
{
    // ping-pong boundary buffers: 9 groups x 4 row-slots x 32 float2 each.
    // group b holds horiz-result rows 8b-2, 8b-1, 8b, 8b+1 (slots 0..3).
    __shared__ float2 sbuf[2][9 * 4 * 32];   // 18 KB

    const int tid  = threadIdx.x;
    const int rb   = tid >> 5;        // 8-row strip index (0..7)
    const int lane = tid & 31;        // float2 column group (0..31)

    const long plane0 = (long)blockIdx.x * PPB;
    const float2* gin  = reinterpret_cast<const float2*>(x)   + plane0 * 2048;
    float2*       gout = reinterpret_cast<float2*>(out)       + plane0 * 2048;

    // Gaussian taps (symmetric), center tap folded to 1; normalize at the end.
    const float sigma = sigma_p[0];
    const float inv2s2 = 1.0f / (2.0f * sigma * sigma);
    const float g0 = expf(-4.0f * inv2s2);   // |d| = 2
    const float g1 = expf(-1.0f * inv2s2);   // |d| = 1
    const float s1 = 2.0f * (g0 + g1) + 1.0f;
    const float invn = 1.0f / (s1 * s1);

    // zero halo rows in BOTH buffers (never overwritten by data):
    // plane rows (-2,-1) -> group 0 slots 0,1 ; rows (64,65) -> group 8 slots 2,3
    {
        int buf = tid >> 7;           // 0/1
        int idx = tid & 127;
        int hr  = idx >> 5;           // 0..3
        int c   = idx & 31;
        int g   = (hr < 2) ? 0 : 8;
        sbuf[buf][(g * 4 + hr) * 32 + c] = make_float2(0.f, 0.f);
    }

    const int base = (rb << 3) * 32 + lane;   // float2 index of (row rb*8, col pair)

    // preload plane 0
    float2 cur[8];
    #pragma unroll
    for (int j = 0; j < 8; j++) cur[j] = gin[base + j * 32];

    #pragma unroll
    for (int p = 0; p < PPB; p++) {
        // issue next plane's loads early (independent of current compute)
        float2 nxt[8];
        if (p + 1 < PPB) {
            #pragma unroll
            for (int j = 0; j < 8; j++) nxt[j] = gin[(p + 1) * 2048 + base + j * 32];
        }

        // --- horizontal pass; boundary rows FIRST so STS fires early ---
        float2 t[8];
        const int horder[8] = {0, 1, 6, 7, 2, 3, 4, 5};
        float2* sp = sbuf[p & 1];
        #pragma unroll
        for (int k = 0; k < 8; k++) {
            int j = horder[k];
            float2 b = cur[j];
            float px = __shfl_up_sync(0xffffffffu, b.x, 1);    // col 2c-2
            float py = __shfl_up_sync(0xffffffffu, b.y, 1);    // col 2c-1
            float nx = __shfl_down_sync(0xffffffffu, b.x, 1);  // col 2c+2
            float ny = __shfl_down_sync(0xffffffffu, b.y, 1);  // col 2c+3
            if (lane == 0)  { px = 0.0f; py = 0.0f; }          // left zero-pad
            if (lane == 31) { nx = 0.0f; ny = 0.0f; }          // right zero-pad
            t[j].x = g0 * (px + nx) + g1 * (py + b.y) + b.x;
            t[j].y = g0 * (py + ny) + g1 * (b.x + nx) + b.y;
            // boundary exchange as soon as each boundary row is ready
            if (k == 0) sp[(rb * 4 + 2) * 32 + lane]       = t[0];   // row 8rb
            if (k == 1) sp[(rb * 4 + 3) * 32 + lane]       = t[1];   // row 8rb+1
            if (k == 2) sp[((rb + 1) * 4 + 0) * 32 + lane] = t[6];   // row 8rb+6
            if (k == 3) sp[((rb + 1) * 4 + 1) * 32 + lane] = t[7];   // row 8rb+7
        }

        float2* go = gout + p * 2048 + base;

        // --- interior output rows (j=2..5): need only local t[0..7] ---
        #pragma unroll
        for (int j = 2; j < 6; j++) {
            float2 o;
            o.x = (g0 * (t[j-2].x + t[j+2].x) + g1 * (t[j-1].x + t[j+1].x) + t[j].x) * invn;
            o.y = (g0 * (t[j-2].y + t[j+2].y) + g1 * (t[j-1].y + t[j+1].y) + t[j].y) * invn;
            __stcs(go + j * 32, o);
        }

        __syncthreads();

        // --- edge output rows (j=0,1,6,7): need halo rows from smem ---
        float2 wm2 = sp[(rb * 4 + 0) * 32 + lane];        // row 8rb-2
        float2 wm1 = sp[(rb * 4 + 1) * 32 + lane];        // row 8rb-1
        float2 wp8 = sp[((rb + 1) * 4 + 2) * 32 + lane];  // row 8rb+8
        float2 wp9 = sp[((rb + 1) * 4 + 3) * 32 + lane];  // row 8rb+9

        float2 o;
        // j = 0: rows -2,-1,0,1,2
        o.x = (g0 * (wm2.x + t[2].x) + g1 * (wm1.x + t[1].x) + t[0].x) * invn;
        o.y = (g0 * (wm2.y + t[2].y) + g1 * (wm1.y + t[1].y) + t[0].y) * invn;
        __stcs(go, o);
        // j = 1: rows -1,0,1,2,3
        o.x = (g0 * (wm1.x + t[3].x) + g1 * (t[0].x + t[2].x) + t[1].x) * invn;
        o.y = (g0 * (wm1.y + t[3].y) + g1 * (t[0].y + t[2].y) + t[1].y) * invn;
        __stcs(go + 32, o);
        // j = 6: rows 4,5,6,7,8
        o.x = (g0 * (t[4].x + wp8.x) + g1 * (t[5].x + t[7].x) + t[6].x) * invn;
        o.y = (g0 * (t[4].y + wp8.y) + g1 * (t[5].y + t[7].y) + t[6].y) * invn;
        __stcs(go + 6 * 32, o);
        // j = 7: rows 5,6,7,8,9
        o.x = (g0 * (t[5].x + wp9.x) + g1 * (t[6].x + wp8.x) + t[7].x) * invn;
        o.y = (g0 * (t[5].y + wp9.y) + g1 * (t[6].y + wp8.y) + t[7].y) * invn;
        __stcs(go + 7 * 32, o);

        // rotate pipeline
        if (p + 1 < PPB) {
            #pragma unroll
            for (int j = 0; j < 8; j++) cur[j] = nxt[j];
        }
    }
}

extern "C" void kernel_launch(void* const* d_in, const int* in_sizes, int n_in,
                              void* d_out, int out_size) {
    const float* x = (const float*)d_in[0];
    const float* sigma = (const float*)d_in[1];
    float* out = (float*)d_out;
    int planes = in_sizes[0] / (HH * WW);   // 4096
    gauss5_kernel<<<planes / PPB, TPB>>>(x, sigma, out);
}